// round 16
// baseline (speedup 1.0000x reference)
#include <cuda_runtime.h>
#include <cuda_fp16.h>
#include <cstdint>

#define B_    8
#define T_    4096
#define R_    1024
#define F_    64
#define I_    32
#define KTOT  96            // F_ + I_
#define NBLK  128           // scan blocks (8 rows of W_hh each)
#define NTHR  256

// ---------------- device scratch (no allocations allowed) ----------------
// epoch-tagged hidden state packets: [buf][k][half] = 16B
//   word0..1: 4 x fp16 h (batches 4*half .. 4*half+3)
//   word2:    epoch (step tag: packet holds h(epoch))
//   word3:    pad
__device__ __align__(16) uint4 g_hp[2][R_][2];

// ---------------- helpers ----------------
__device__ __forceinline__ unsigned long long pack2(float a, float b) {
    unsigned long long r;
    asm("mov.b64 %0, {%1, %2};" : "=l"(r) : "f"(a), "f"(b));
    return r;
}
__device__ __forceinline__ void fma2(unsigned long long& d, unsigned long long a, unsigned long long b) {
    asm("fma.rn.f32x2 %0, %1, %2, %0;" : "+l"(d) : "l"(a), "l"(b));
}
__device__ __forceinline__ unsigned long long add2(unsigned long long a, unsigned long long b) {
    unsigned long long r;
    asm("add.rn.f32x2 %0, %1, %2;" : "=l"(r) : "l"(a), "l"(b));
    return r;
}
__device__ __forceinline__ float2 unpack2(unsigned long long v) {
    float2 f;
    asm("mov.b64 {%0, %1}, %2;" : "=f"(f.x), "=f"(f.y) : "l"(v));
    return f;
}
__device__ __forceinline__ float tanh_fast(float x) {
    float y;
    asm("tanh.approx.f32 %0, %1;" : "=f"(y) : "f"(x));
    return y;
}

template <int HALF>
__device__ __forceinline__ void reduce_round(unsigned long long* a, int lane, int d) {
    const bool hi = (lane & d) != 0;
#pragma unroll
    for (int i = 0; i < HALF; i++) {
        unsigned long long send = hi ? a[i] : a[i + HALF];
        unsigned long long keep = hi ? a[i + HALF] : a[i];
        unsigned long long recv = __shfl_xor_sync(0xffffffffu, send, d);
        a[i] = add2(keep, recv);
    }
}

// ---------------- drive GEMM (+ folded reset): out[bt][r] = X @ [Wfb|Win]^T + b ----
#define DRIVE_SMEM ((64 + 128) * 97 * 4)

__global__ __launch_bounds__(256) void drive_kernel(
    const float* __restrict__ fb, const float* __restrict__ drv,
    const float* __restrict__ Wfb, const float* __restrict__ Win,
    const float* __restrict__ bias, float* __restrict__ out)
{
    extern __shared__ float smem[];
    float (*xs)[97]  = (float (*)[97])smem;              // [64][97]
    float (*wsh)[97] = (float (*)[97])(smem + 64 * 97);  // [128][97]

    const int r0  = blockIdx.x * 128;
    const int bt0 = blockIdx.y * 64;
    const int tid = threadIdx.x;

    // folded reset (blocks y==0): zero everything.
    // buf0 packets: h=0, epoch=0  -> valid h(0)
    // buf1 packets: epoch=0 != 1  -> invalid until written at end of step 0
    if (blockIdx.y == 0) {
        uint4* p = &g_hp[0][0][0];
        const int n = 2 * R_ * 2;           // 4096 uint4
        const int chunk = n / 8;            // 512 per block
        for (int i = tid; i < chunk; i += 256)
            p[blockIdx.x * chunk + i] = make_uint4(0u, 0u, 0u, 0u);
    }

    for (int idx = tid; idx < 64 * KTOT; idx += 256) {
        int row = idx / KTOT, col = idx - row * KTOT;
        float v = (col < F_) ? fb[(size_t)(bt0 + row) * F_ + col]
                             : drv[(size_t)(bt0 + row) * I_ + (col - F_)];
        xs[row][col] = v;
    }
    for (int idx = tid; idx < 128 * KTOT; idx += 256) {
        int row = idx / KTOT, col = idx - row * KTOT;
        int r = r0 + row;
        float v = (col < F_) ? Wfb[r * F_ + col] : Win[r * I_ + (col - F_)];
        wsh[row][col] = v;
    }
    __syncthreads();

    const int tx = tid & 15;
    const int ty = tid >> 4;

    float acc[4][8];
#pragma unroll
    for (int i = 0; i < 4; i++)
#pragma unroll
        for (int j = 0; j < 8; j++) acc[i][j] = 0.0f;

    for (int f = 0; f < KTOT; f++) {
        float x0 = xs[ty * 4 + 0][f];
        float x1 = xs[ty * 4 + 1][f];
        float x2 = xs[ty * 4 + 2][f];
        float x3 = xs[ty * 4 + 3][f];
        float w[8];
#pragma unroll
        for (int j = 0; j < 8; j++) w[j] = wsh[tx + 16 * j][f];
#pragma unroll
        for (int j = 0; j < 8; j++) {
            acc[0][j] = fmaf(x0, w[j], acc[0][j]);
            acc[1][j] = fmaf(x1, w[j], acc[1][j]);
            acc[2][j] = fmaf(x2, w[j], acc[2][j]);
            acc[3][j] = fmaf(x3, w[j], acc[3][j]);
        }
    }

#pragma unroll
    for (int j = 0; j < 8; j++) {
        int r = r0 + tx + 16 * j;
        float bv = bias[r];
#pragma unroll
        for (int i = 0; i < 4; i++) {
            size_t bt = (size_t)bt0 + ty * 4 + i;
            out[bt * R_ + r] = acc[i][j] + bv;
        }
    }
}

// ---------------- sequential scan: epoch-tagged packets, no flag barrier ---------
__global__ __launch_bounds__(NTHR, 1) void scan_kernel(
    const float* __restrict__ Whh, float* __restrict__ out)
{
    __shared__ float2 partials[8][32];

    const int tid  = threadIdx.x;
    const int lane = tid & 31;
    const int warp = tid >> 5;
    const int r0   = blockIdx.x * 8;
    const int half = tid & 1;
    const int kq   = tid >> 1;

    // preload W_hh slice, duplicated pairs {w,w} (registers)
    unsigned long long wd[8][8];
#pragma unroll
    for (int i = 0; i < 8; i++) {
        int k = kq + i * 128;
#pragma unroll
        for (int j = 0; j < 8; j++) {
            float w = Whh[(size_t)(r0 + j) * R_ + k];
            wd[i][j] = pack2(w, w);
        }
    }

    const float alpha = 0.9f;
    const float onem  = 1.0f - alpha;

    size_t oi0 = 0, oi1 = 0;
    float hprev0 = 0.0f, hprev1 = 0.0f;
    float pv0 = 0.0f, pv1 = 0.0f;        // deferred out-store values
    int er = 0, eb0 = 0, ep = 0;
    uint4* my_pkt = nullptr;             // this lane's packet (row er, half ep>>1)
    int my_slot = 0;                     // word slot within packet (0 or 1)
    if (warp == 0) {
        int j = lane >> 2;
        ep = lane & 3;                   // batch-pair index 0..3
        er = r0 + j; eb0 = 2 * ep;
        oi0 = ((size_t)eb0 * T_) * R_ + er;
        oi1 = ((size_t)(eb0 + 1) * T_) * R_ + er;
        my_pkt  = &g_hp[0][er][ep >> 1];  // buffer selected per step
        my_slot = ep & 1;
    }

    for (int t = 0; t < T_; t++) {
        const int cur = t & 1, nxt = cur ^ 1;

        // ---- u(t) load + deferred out store (overlaps packet polling) ----
        float u0 = 0.0f, u1 = 0.0f;
        if (warp == 0) {
            u0 = __ldcs(&out[oi0 + (size_t)t * R_]);
            u1 = __ldcs(&out[oi1 + (size_t)t * R_]);
            if (t > 0) {
                __stcg(&out[oi0 + (size_t)(t - 1) * R_], pv0);
                __stcg(&out[oi1 + (size_t)(t - 1) * R_], pv1);
            }
        }

        // ---- poll packets (the store IS the flag); FMA fused on arrival ----
        unsigned long long acc[16];
#pragma unroll
        for (int o = 0; o < 16; o++) acc[o] = 0ull;

        const uint4* src = &g_hp[cur][0][half];
        unsigned vm = 0;
        const unsigned epoch = (unsigned)t;
        while (vm != 0xFFu) {
#pragma unroll
            for (int i = 0; i < 8; i++) {
                if (!((vm >> i) & 1u)) {
                    const uint4* p = src + (kq + i * 128) * 2;
                    uint4 v;
                    asm volatile("ld.global.cg.v4.u32 {%0,%1,%2,%3}, [%4];"
                                 : "=r"(v.x), "=r"(v.y), "=r"(v.z), "=r"(v.w)
                                 : "l"(p) : "memory");
                    if (v.z == epoch) {
                        vm |= (1u << i);
                        float2 fa = __half22float2(*reinterpret_cast<__half2*>(&v.x));
                        float2 fb = __half22float2(*reinterpret_cast<__half2*>(&v.y));
                        unsigned long long h01 = pack2(fa.x, fa.y);
                        unsigned long long h23 = pack2(fb.x, fb.y);
#pragma unroll
                        for (int j = 0; j < 8; j++) {
                            fma2(acc[j * 2 + 0], h01, wd[i][j]);
                            fma2(acc[j * 2 + 1], h23, wd[i][j]);
                        }
                    }
                }
            }
        }

        // ---- log-halving warp reduction ----
        reduce_round<8>(acc, lane, 2);
        reduce_round<4>(acc, lane, 4);
        reduce_round<2>(acc, lane, 8);
        reduce_round<1>(acc, lane, 16);

        {
            int o = (((lane >> 1) & 1) << 3) | (((lane >> 2) & 1) << 2) |
                    (((lane >> 3) & 1) << 1) | ((lane >> 4) & 1);
            int j = o >> 1, q = o & 1;
            int p = 2 * half + q;
            partials[warp][j * 4 + p] = unpack2(acc[0]);
        }
        __syncthreads();                                   // (A) the only barrier

        // ---- epilogue: warp0 tree-add + tanh + packet publish ----
        if (warp == 0) {
            float2 p0 = partials[0][lane], p1 = partials[1][lane];
            float2 p2 = partials[2][lane], p3 = partials[3][lane];
            float2 p4 = partials[4][lane], p5 = partials[5][lane];
            float2 p6 = partials[6][lane], p7 = partials[7][lane];
            float sx = ((p0.x + p1.x) + (p2.x + p3.x)) + ((p4.x + p5.x) + (p6.x + p7.x));
            float sy = ((p0.y + p1.y) + (p2.y + p3.y)) + ((p4.y + p5.y) + (p6.y + p7.y));

            float v0 = tanh_fast(onem * hprev0 + alpha * (u0 + sx));
            float v1 = tanh_fast(onem * hprev1 + alpha * (u1 + sy));
            hprev0 = v0; hprev1 = v1;
            pv0 = v0; pv1 = v1;

            // write h words into next-buffer packet, then release epoch
            __half2 hv = __floats2half2_rn(v0, v1);
            unsigned hb = *reinterpret_cast<unsigned*>(&hv);
            unsigned* pkt = reinterpret_cast<unsigned*>(
                &g_hp[nxt][er][ep >> 1]);
            __stcg(pkt + my_slot, hb);          // word 0 or 1
            __syncwarp();                        // both slots' h before epoch
            if (my_slot == 0) {
                asm volatile("st.release.gpu.global.u32 [%0], %1;"
                             :: "l"(pkt + 2), "r"((unsigned)(t + 1)) : "memory");
            }
        }
    }

    // final out store for t = T-1
    if (warp == 0) {
        __stcg(&out[oi0 + (size_t)(T_ - 1) * R_], pv0);
        __stcg(&out[oi1 + (size_t)(T_ - 1) * R_], pv1);
    }
}

// ---------------- launch ----------------
extern "C" void kernel_launch(void* const* d_in, const int* in_sizes, int n_in,
                              void* d_out, int out_size)
{
    (void)in_sizes; (void)n_in; (void)out_size;
    const float* fb   = (const float*)d_in[0];
    const float* drv  = (const float*)d_in[1];
    const float* Wfb  = (const float*)d_in[2];
    const float* Win  = (const float*)d_in[3];
    const float* Whh  = (const float*)d_in[4];
    const float* bias = (const float*)d_in[5];
    float* out = (float*)d_out;

    cudaFuncSetAttribute(drive_kernel, cudaFuncAttributeMaxDynamicSharedMemorySize, DRIVE_SMEM);

    dim3 dgrid(R_ / 128, (B_ * T_) / 64);
    drive_kernel<<<dgrid, 256, DRIVE_SMEM>>>(fb, drv, Wfb, Win, bias, out);

    scan_kernel<<<NBLK, NTHR>>>(Whh, out);
}